// round 1
// baseline (speedup 1.0000x reference)
#include <cuda_runtime.h>
#include <math.h>

#define NT  32768
#define CC  128
#define BB  64
#define NNODE 512
#define HH  4
#define DHD 32
#define EE  524288

// ---------------- scratch (device globals; no allocation allowed) ----------------
__device__ float g_agg[NT*CC];
__device__ int   g_deg[NT];
__device__ int   g_off[NT+1];
__device__ int   g_cur[NT];
__device__ int   g_nbr[EE];
__device__ float g_hlocal[NT*CC];
__device__ float g_q[NT*CC];      // [B,H,N,DH]
__device__ float g_kbuf[NT*CC];   // [B,H,N,DH]
__device__ float g_vbuf[NT*CC];   // [B,H,N,DH]
__device__ float g_obuf[NT*CC];   // [NT, C] (head-concat)
__device__ float g_hattn[NT*CC];
__device__ float g_comb[NT*CC];
__device__ float g_hidden[NT*2*CC];
__device__ float g_out2[NT*CC];
__device__ float g_sums[3*2*CC];  // per-bn: sum[128], sumsq[128]
__device__ float g_scale[3*CC];
__device__ float g_shift[3*CC];

// ---------------- CSR build ----------------
__global__ void k_zero() {
    int i = blockIdx.x * blockDim.x + threadIdx.x;
    if (i < NT) g_deg[i] = 0;
    if (i < 3*2*CC) g_sums[i] = 0.f;
}

__global__ void k_deg(const int* __restrict__ dst) {
    int i = blockIdx.x * blockDim.x + threadIdx.x;
    if (i < EE) atomicAdd(&g_deg[dst[i]], 1);
}

__global__ void k_scan() {   // 1 block, 1024 threads, NT/1024 = 32 per thread
    __shared__ int ssum[1024];
    int t = threadIdx.x;
    int base = t * 32;
    int s = 0;
    #pragma unroll
    for (int i = 0; i < 32; i++) s += g_deg[base + i];
    ssum[t] = s;
    __syncthreads();
    for (int off = 1; off < 1024; off <<= 1) {
        int tmp = (t >= off) ? ssum[t - off] : 0;
        __syncthreads();
        ssum[t] += tmp;
        __syncthreads();
    }
    int run = ssum[t] - s;  // exclusive prefix of this chunk
    #pragma unroll
    for (int i = 0; i < 32; i++) {
        g_off[base + i] = run;
        g_cur[base + i] = run;
        run += g_deg[base + i];
    }
    if (t == 1023) g_off[NT] = run;
}

__global__ void k_fill(const int* __restrict__ src, const int* __restrict__ dst) {
    int i = blockIdx.x * blockDim.x + threadIdx.x;
    if (i < EE) {
        int p = atomicAdd(&g_cur[dst[i]], 1);
        g_nbr[p] = src[i];
    }
}

// ---------------- mean aggregation (gather) ----------------
__global__ void k_agg(const float* __restrict__ x) {
    __shared__ int snbr[128];
    int n = blockIdx.x, c = threadIdx.x;
    int s0 = g_off[n], s1 = g_off[n+1];
    float acc = 0.f;
    for (int j0 = s0; j0 < s1; j0 += 128) {
        int m = min(128, s1 - j0);
        __syncthreads();
        if (c < m) snbr[c] = g_nbr[j0 + c];
        __syncthreads();
        for (int jj = 0; jj < m; jj++) acc += x[snbr[jj]*CC + c];
    }
    float d = (float)(s1 - s0);
    g_agg[n*CC + c] = acc / fmaxf(d, 1.f);
}

// ---------------- register-blocked SGEMM: out[M,N] = A[M,K] @ W[N,K]^T ----------------
// EPI: 0 = +bias ; 1 = +bias+resid ; 2 = +bias+relu ; 3 = +bias, scatter QKV
template<int EPI>
__global__ __launch_bounds__(256) void k_gemm(const float* __restrict__ A,
                                              const float* __restrict__ W,
                                              const float* __restrict__ bias,
                                              const float* __restrict__ resid,
                                              float* __restrict__ out,
                                              int M, int Nn, int K) {
    __shared__ float As[16][64];
    __shared__ float Ws[16][64];
    int t = threadIdx.x;
    int bm = blockIdx.x, bn = blockIdx.y;
    int lr = t >> 2;          // 0..63
    int lc = (t & 3) << 2;    // 0,4,8,12
    const float* Aptr = A + (size_t)(bm*64 + lr) * K + lc;
    const float* Wptr = W + (size_t)(bn*64 + lr) * K + lc;
    int tm = (t >> 4) << 2;   // 0..60
    int tn = (t & 15) << 2;   // 0..60
    float acc[4][4] = {};
    for (int k0 = 0; k0 < K; k0 += 16) {
        float4 av = *(const float4*)(Aptr + k0);
        float4 wv = *(const float4*)(Wptr + k0);
        As[lc+0][lr] = av.x; As[lc+1][lr] = av.y; As[lc+2][lr] = av.z; As[lc+3][lr] = av.w;
        Ws[lc+0][lr] = wv.x; Ws[lc+1][lr] = wv.y; Ws[lc+2][lr] = wv.z; Ws[lc+3][lr] = wv.w;
        __syncthreads();
        #pragma unroll
        for (int kk = 0; kk < 16; kk++) {
            float4 a = *(const float4*)(&As[kk][tm]);
            float4 b = *(const float4*)(&Ws[kk][tn]);
            float ar[4] = {a.x, a.y, a.z, a.w};
            float br[4] = {b.x, b.y, b.z, b.w};
            #pragma unroll
            for (int i = 0; i < 4; i++)
                #pragma unroll
                for (int j = 0; j < 4; j++)
                    acc[i][j] += ar[i] * br[j];
        }
        __syncthreads();
    }
    int row0 = bm*64 + tm;
    int col0 = bn*64 + tn;
    float4 bv = *(const float4*)(bias + col0);
    if (EPI == 3) {
        int which = col0 >> 7;        // 0=q,1=k,2=v (col group of 4 never crosses)
        int cbase = col0 & 127;
        int h = cbase >> 5, d = cbase & 31;
        float* dp = (which == 0) ? g_q : ((which == 1) ? g_kbuf : g_vbuf);
        #pragma unroll
        for (int i = 0; i < 4; i++) {
            int m = row0 + i;
            int bq = m >> 9, nq = m & 511;
            float4 v = make_float4(acc[i][0]+bv.x, acc[i][1]+bv.y, acc[i][2]+bv.z, acc[i][3]+bv.w);
            *(float4*)(dp + ((size_t)(bq*HH + h)*NNODE + nq)*DHD + d) = v;
        }
    } else {
        #pragma unroll
        for (int i = 0; i < 4; i++) {
            int m = row0 + i;
            float4 v = make_float4(acc[i][0]+bv.x, acc[i][1]+bv.y, acc[i][2]+bv.z, acc[i][3]+bv.w);
            if (EPI == 1) {
                float4 rv = *(const float4*)(resid + (size_t)m*Nn + col0);
                v.x += rv.x; v.y += rv.y; v.z += rv.z; v.w += rv.w;
            }
            if (EPI == 2) {
                v.x = fmaxf(v.x, 0.f); v.y = fmaxf(v.y, 0.f);
                v.z = fmaxf(v.z, 0.f); v.w = fmaxf(v.w, 0.f);
            }
            *(float4*)(out + (size_t)m*Nn + col0) = v;
        }
    }
}

// ---------------- attention: one block per (b,h) ----------------
#define KT_S 516
#define S_S  516
#define QT_S 36
#define ATTN_SMEM ((32*KT_S + 512*32 + 32*S_S + 32*QT_S + 4096) * 4)

__global__ __launch_bounds__(256, 1) void k_attn() {
    extern __shared__ float sm[];
    float* Kt  = sm;                   // [32][516]   Kt[d][j]
    float* Vs  = Kt + 32*KT_S;         // [512][32]   Vs[j][d]
    float* S   = Vs + 512*32;          // [32][516]   S[qi][j]
    float* Qt  = S + 32*S_S;           // [32][36]    Qt[d][qi]
    float* Red = Qt + 32*QT_S;         // [4][32][32]
    int bh = blockIdx.x;
    int t  = threadIdx.x;
    const float* kb = g_kbuf + (size_t)bh * NNODE * DHD;
    const float* vb = g_vbuf + (size_t)bh * NNODE * DHD;
    const float* qb = g_q    + (size_t)bh * NNODE * DHD;
    int b = bh >> 2, h = bh & 3;

    // load K (transposed) and V
    for (int i = t; i < NNODE*8; i += 256) {
        int j  = i >> 3;
        int d4 = (i & 7) << 2;
        float4 kv = *(const float4*)(kb + j*DHD + d4);
        Kt[(d4+0)*KT_S + j] = kv.x;
        Kt[(d4+1)*KT_S + j] = kv.y;
        Kt[(d4+2)*KT_S + j] = kv.z;
        Kt[(d4+3)*KT_S + j] = kv.w;
        *(float4*)(Vs + j*DHD + d4) = *(const float4*)(vb + j*DHD + d4);
    }
    __syncthreads();

    const float sc = 0.17677669529663687f; // 1/sqrt(32)
    for (int qt = 0; qt < 16; qt++) {
        // load Q tile transposed
        for (int i = t; i < 1024; i += 256) {
            int qi = i >> 5, d = i & 31;
            Qt[d*QT_S + qi] = qb[(qt*32 + qi)*DHD + d];
        }
        __syncthreads();
        // scores: S[32][512] = Qt^T @ Kt, 8x8 register tile
        {
            int qg = t >> 6, jg = t & 63;
            float acc[8][8] = {};
            #pragma unroll 4
            for (int kk = 0; kk < 32; kk++) {
                float4 a0 = *(const float4*)(Qt + kk*QT_S + qg*8);
                float4 a1 = *(const float4*)(Qt + kk*QT_S + qg*8 + 4);
                float4 b0 = *(const float4*)(Kt + kk*KT_S + jg*8);
                float4 b1 = *(const float4*)(Kt + kk*KT_S + jg*8 + 4);
                float av[8] = {a0.x,a0.y,a0.z,a0.w,a1.x,a1.y,a1.z,a1.w};
                float bw[8] = {b0.x,b0.y,b0.z,b0.w,b1.x,b1.y,b1.z,b1.w};
                #pragma unroll
                for (int i = 0; i < 8; i++)
                    #pragma unroll
                    for (int j = 0; j < 8; j++)
                        acc[i][j] += av[i] * bw[j];
            }
            #pragma unroll
            for (int i = 0; i < 8; i++) {
                float* srow = S + (qg*8 + i)*S_S + jg*8;
                *(float4*)(srow)     = make_float4(acc[i][0]*sc, acc[i][1]*sc, acc[i][2]*sc, acc[i][3]*sc);
                *(float4*)(srow + 4) = make_float4(acc[i][4]*sc, acc[i][5]*sc, acc[i][6]*sc, acc[i][7]*sc);
            }
        }
        __syncthreads();
        // softmax per row (warp per row, 4 rows per warp)
        {
            int w = t >> 5, lane = t & 31;
            for (int rr = 0; rr < 4; rr++) {
                int qi = w*4 + rr;
                float* row = S + qi*S_S;
                float vals[16];
                float mx = -1e30f;
                #pragma unroll
                for (int ii = 0; ii < 16; ii++) {
                    vals[ii] = row[lane + 32*ii];
                    mx = fmaxf(mx, vals[ii]);
                }
                #pragma unroll
                for (int o = 16; o > 0; o >>= 1) mx = fmaxf(mx, __shfl_xor_sync(0xffffffffu, mx, o));
                float sum = 0.f;
                #pragma unroll
                for (int ii = 0; ii < 16; ii++) { vals[ii] = __expf(vals[ii] - mx); sum += vals[ii]; }
                #pragma unroll
                for (int o = 16; o > 0; o >>= 1) sum += __shfl_xor_sync(0xffffffffu, sum, o);
                float inv = 1.f / sum;
                #pragma unroll
                for (int ii = 0; ii < 16; ii++) row[lane + 32*ii] = vals[ii] * inv;
            }
        }
        __syncthreads();
        // O = P @ V with j-split (4 slices), 4x4 register tile
        {
            int js = t >> 6, r = t & 63, qg = r >> 3, dg = r & 7;
            float acc[4][4] = {};
            int j0 = js * 128;
            for (int j = j0; j < j0 + 128; j++) {
                float4 vv = *(const float4*)(Vs + j*32 + dg*4);
                #pragma unroll
                for (int i = 0; i < 4; i++) {
                    float p = S[(qg*4 + i)*S_S + j];
                    acc[i][0] += p*vv.x; acc[i][1] += p*vv.y;
                    acc[i][2] += p*vv.z; acc[i][3] += p*vv.w;
                }
            }
            #pragma unroll
            for (int i = 0; i < 4; i++)
                *(float4*)(Red + js*1024 + (qg*4 + i)*32 + dg*4) =
                    make_float4(acc[i][0], acc[i][1], acc[i][2], acc[i][3]);
        }
        __syncthreads();
        // reduce partials, store to g_obuf [NT, C]
        {
            int qi = t >> 3, d4 = (t & 7) << 2;
            float4 r0 = *(const float4*)(Red +        qi*32 + d4);
            float4 r1 = *(const float4*)(Red + 1024 + qi*32 + d4);
            float4 r2 = *(const float4*)(Red + 2048 + qi*32 + d4);
            float4 r3 = *(const float4*)(Red + 3072 + qi*32 + d4);
            float4 o4 = make_float4(r0.x+r1.x+r2.x+r3.x, r0.y+r1.y+r2.y+r3.y,
                                    r0.z+r1.z+r2.z+r3.z, r0.w+r1.w+r2.w+r3.w);
            int nq = qt*32 + qi;
            *(float4*)(g_obuf + ((size_t)(b*NNODE + nq))*CC + h*DHD + d4) = o4;
        }
        __syncthreads();
    }
}

// ---------------- batchnorm stats / finalize / apply ----------------
__global__ void k_stats(const float* __restrict__ buf, int which) {
    int t = threadIdx.x;
    int c = t & 127, half = t >> 7;
    const float* p = buf + ((size_t)blockIdx.x*256 + half)*CC + c;
    float s = 0.f, s2 = 0.f;
    #pragma unroll 4
    for (int i = 0; i < 128; i++) {
        float v = p[(size_t)i*256];
        s += v; s2 += v*v;
    }
    __shared__ float sh[2][256];
    sh[0][t] = s; sh[1][t] = s2;
    __syncthreads();
    if (t < 128) {
        atomicAdd(&g_sums[which*256 + t],       sh[0][t] + sh[0][t+128]);
        atomicAdd(&g_sums[which*256 + 128 + t], sh[1][t] + sh[1][t+128]);
    }
}

__global__ void k_finalize(int which, const float* __restrict__ g, const float* __restrict__ b) {
    int c = threadIdx.x;
    float s  = g_sums[which*256 + c];
    float s2 = g_sums[which*256 + 128 + c];
    float m  = s / (float)NT;
    float v  = s2 / (float)NT - m*m;
    float scale = g[c] * rsqrtf(v + 1e-5f);
    g_scale[which*128 + c] = scale;
    g_shift[which*128 + c] = b[c] - m*scale;
}

__global__ void k_combine() {   // g_comb = bn1(g_hlocal) + bn2(g_hattn)
    int i = blockIdx.x * blockDim.x + threadIdx.x;   // float4 index
    int c = (i*4) & 127;
    float4 a  = *(const float4*)(g_hlocal + (size_t)i*4);
    float4 bb = *(const float4*)(g_hattn + (size_t)i*4);
    float4 s1 = *(const float4*)(g_scale + c);
    float4 h1 = *(const float4*)(g_shift + c);
    float4 s2 = *(const float4*)(g_scale + 128 + c);
    float4 h2 = *(const float4*)(g_shift + 128 + c);
    float4 o;
    o.x = a.x*s1.x + h1.x + bb.x*s2.x + h2.x;
    o.y = a.y*s1.y + h1.y + bb.y*s2.y + h2.y;
    o.z = a.z*s1.z + h1.z + bb.z*s2.z + h2.z;
    o.w = a.w*s1.w + h1.w + bb.w*s2.w + h2.w;
    *(float4*)(g_comb + (size_t)i*4) = o;
}

__global__ void k_final(float* __restrict__ out) {   // out = bn3(g_out2)
    int i = blockIdx.x * blockDim.x + threadIdx.x;
    int c = (i*4) & 127;
    float4 a  = *(const float4*)(g_out2 + (size_t)i*4);
    float4 s3 = *(const float4*)(g_scale + 256 + c);
    float4 h3 = *(const float4*)(g_shift + 256 + c);
    float4 o;
    o.x = a.x*s3.x + h3.x;
    o.y = a.y*s3.y + h3.y;
    o.z = a.z*s3.z + h3.z;
    o.w = a.w*s3.w + h3.w;
    *(float4*)(out + (size_t)i*4) = o;
}

// ---------------- launch ----------------
extern "C" void kernel_launch(void* const* d_in, const int* in_sizes, int n_in,
                              void* d_out, int out_size) {
    const float* x   = (const float*)d_in[0];
    const int*   ei  = (const int*)  d_in[1];
    const float* Wc  = (const float*)d_in[2];
    const float* bc  = (const float*)d_in[3];
    const float* ipw = (const float*)d_in[4];
    const float* ipb = (const float*)d_in[5];
    const float* opw = (const float*)d_in[6];
    const float* opb = (const float*)d_in[7];
    const float* gn1 = (const float*)d_in[8];
    const float* bn1 = (const float*)d_in[9];
    const float* gn2 = (const float*)d_in[10];
    const float* bn2 = (const float*)d_in[11];
    const float* gn3 = (const float*)d_in[12];
    const float* bn3 = (const float*)d_in[13];
    const float* Wm1 = (const float*)d_in[14];
    const float* bm1 = (const float*)d_in[15];
    const float* Wm2 = (const float*)d_in[16];
    const float* bm2 = (const float*)d_in[17];
    const int* src = ei;
    const int* dst = ei + EE;

    void *p_agg, *p_hlocal, *p_o, *p_hattn, *p_comb, *p_hidden, *p_out2;
    cudaGetSymbolAddress(&p_agg,    g_agg);
    cudaGetSymbolAddress(&p_hlocal, g_hlocal);
    cudaGetSymbolAddress(&p_o,      g_obuf);
    cudaGetSymbolAddress(&p_hattn,  g_hattn);
    cudaGetSymbolAddress(&p_comb,   g_comb);
    cudaGetSymbolAddress(&p_hidden, g_hidden);
    cudaGetSymbolAddress(&p_out2,   g_out2);

    cudaFuncSetAttribute(k_attn, cudaFuncAttributeMaxDynamicSharedMemorySize, ATTN_SMEM);

    k_zero<<<NT/256, 256>>>();
    k_deg<<<EE/256, 256>>>(dst);
    k_scan<<<1, 1024>>>();
    k_fill<<<EE/256, 256>>>(src, dst);
    k_agg<<<NT, 128>>>(x);

    dim3 gLocal(NT/64, 2);
    k_gemm<1><<<gLocal, 256>>>((const float*)p_agg, Wc, bc, x, (float*)p_hlocal, NT, 128, 128);

    dim3 gQKV(NT/64, 6);
    k_gemm<3><<<gQKV, 256>>>(x, ipw, ipb, nullptr, nullptr, NT, 384, 128);

    k_attn<<<BB*HH, 256, ATTN_SMEM>>>();

    k_gemm<1><<<gLocal, 256>>>((const float*)p_o, opw, opb, x, (float*)p_hattn, NT, 128, 128);

    k_stats<<<NT/256, 256>>>((const float*)p_hlocal, 0);
    k_stats<<<NT/256, 256>>>((const float*)p_hattn, 1);
    k_finalize<<<1, 128>>>(0, gn1, bn1);
    k_finalize<<<1, 128>>>(1, gn2, bn2);

    k_combine<<<NT*CC/4/256, 256>>>();

    dim3 gMlp1(NT/64, 4);
    k_gemm<2><<<gMlp1, 256>>>((const float*)p_comb, Wm1, bm1, nullptr, (float*)p_hidden, NT, 256, 128);
    dim3 gMlp2(NT/64, 2);
    k_gemm<1><<<gMlp2, 256>>>((const float*)p_hidden, Wm2, bm2, (const float*)p_comb, (float*)p_out2, NT, 128, 256);

    k_stats<<<NT/256, 256>>>((const float*)p_out2, 2);
    k_finalize<<<1, 128>>>(2, gn3, bn3);
    k_final<<<NT*CC/4/256, 256>>>((float*)d_out);
}

// round 4
// speedup vs baseline: 1.1948x; 1.1948x over previous
#include <cuda_runtime.h>
#include <cuda_bf16.h>
#include <math.h>
#include <stdint.h>

#define NT  32768
#define CC  128
#define BB  64
#define NNODE 512
#define HH  4
#define DHD 32
#define EE  524288

// ---------------- scratch (device globals; no allocation allowed) ----------------
__device__ int   g_deg[NT];
__device__ int   g_off[NT+1];
__device__ int   g_cur[NT];
__device__ int   g_nbr[EE];
__device__ float g_hlocal[NT*CC];
__device__ float g_q[NT*CC];      // [B,H,N,DH]
__device__ float g_kbuf[NT*CC];   // [B,H,N,DH]
__device__ float g_vbuf[NT*CC];   // [B,H,N,DH]
__device__ float g_hattn[NT*CC];
__device__ float g_comb[NT*CC];
__device__ float g_out2[NT*CC];
__device__ float g_sums[3*2*CC];
__device__ float g_scale[3*CC];
__device__ float g_shift[3*CC];

// bf16 split buffers: layout [rows, 3K] = [hi | lo | hi] (A-side) or [hi | hi | lo] (W-side)
__device__ __nv_bfloat16 g_xs[NT*384];
__device__ __nv_bfloat16 g_aggs[NT*384];
__device__ __nv_bfloat16 g_obufs[NT*384];
__device__ __nv_bfloat16 g_combs[NT*384];
__device__ __nv_bfloat16 g_hiddens[NT*768];
__device__ __nv_bfloat16 g_Wcs[128*384];
__device__ __nv_bfloat16 g_ipws[384*384];
__device__ __nv_bfloat16 g_opws[128*384];
__device__ __nv_bfloat16 g_Wm1s[256*384];
__device__ __nv_bfloat16 g_Wm2s[128*768];

// ---------------- helpers ----------------
__device__ __forceinline__ uint32_t smem_u32(const void* p) {
    uint32_t a;
    asm("{ .reg .u64 t; cvta.to.shared.u64 t, %1; cvt.u32.u64 %0, t; }" : "=r"(a) : "l"(p));
    return a;
}
__device__ __forceinline__ uint32_t pack_bf2(__nv_bfloat16 a, __nv_bfloat16 b) {
    return (uint32_t)__bfloat16_as_ushort(a) | ((uint32_t)__bfloat16_as_ushort(b) << 16);
}
__device__ __forceinline__ void split_bf(float v, __nv_bfloat16& hi, __nv_bfloat16& lo) {
    hi = __float2bfloat16(v);
    lo = __float2bfloat16(v - __bfloat162float(hi));
}

// ---------------- CSR build ----------------
__global__ void k_zero() {
    int i = blockIdx.x * blockDim.x + threadIdx.x;
    if (i < NT) g_deg[i] = 0;
    if (i < 3*2*CC) g_sums[i] = 0.f;
}
__global__ void k_deg(const int* __restrict__ dst) {
    int i = blockIdx.x * blockDim.x + threadIdx.x;
    if (i < EE) atomicAdd(&g_deg[dst[i]], 1);
}
__global__ void k_scan() {
    __shared__ int ssum[1024];
    int t = threadIdx.x;
    int base = t * 32;
    int s = 0;
    #pragma unroll
    for (int i = 0; i < 32; i++) s += g_deg[base + i];
    ssum[t] = s;
    __syncthreads();
    for (int off = 1; off < 1024; off <<= 1) {
        int tmp = (t >= off) ? ssum[t - off] : 0;
        __syncthreads();
        ssum[t] += tmp;
        __syncthreads();
    }
    int run = ssum[t] - s;
    #pragma unroll
    for (int i = 0; i < 32; i++) {
        g_off[base + i] = run;
        g_cur[base + i] = run;
        run += g_deg[base + i];
    }
    if (t == 1023) g_off[NT] = run;
}
__global__ void k_fill(const int* __restrict__ src, const int* __restrict__ dst) {
    int i = blockIdx.x * blockDim.x + threadIdx.x;
    if (i < EE) {
        int p = atomicAdd(&g_cur[dst[i]], 1);
        g_nbr[p] = src[i];
    }
}

// ---------------- mean aggregation (gather) -> split bf16 ----------------
__global__ void k_agg(const float* __restrict__ x) {
    __shared__ int snbr[128];
    int n = blockIdx.x, c = threadIdx.x;
    int s0 = g_off[n], s1 = g_off[n+1];
    float acc = 0.f;
    for (int j0 = s0; j0 < s1; j0 += 128) {
        int m = min(128, s1 - j0);
        __syncthreads();
        if (c < m) snbr[c] = g_nbr[j0 + c];
        __syncthreads();
        for (int jj = 0; jj < m; jj++) acc += x[snbr[jj]*CC + c];
    }
    float d = (float)(s1 - s0);
    float v = acc / fmaxf(d, 1.f);
    __nv_bfloat16 hi, lo; split_bf(v, hi, lo);
    size_t base = (size_t)n * 384;
    g_aggs[base + c] = hi;
    g_aggs[base + 128 + c] = lo;
    g_aggs[base + 256 + c] = hi;
}

// ---------------- split kernels ----------------
// A-side: [hi | lo | hi]
template<int LOGK>
__global__ void k_split(const float* __restrict__ in, __nv_bfloat16* __restrict__ out, int total) {
    int i = blockIdx.x * blockDim.x + threadIdx.x;
    if (i >= total) return;
    const int K = 1 << LOGK;
    int r = i >> LOGK, c = i & (K-1);
    float v = in[i];
    __nv_bfloat16 hi, lo; split_bf(v, hi, lo);
    __nv_bfloat16* o = out + ((size_t)(3*r) << LOGK);
    o[c] = hi; o[K + c] = lo; o[2*K + c] = hi;
}
// W-side: [hi | hi | lo]
template<int LOGK>
__global__ void k_splitw(const float* __restrict__ in, __nv_bfloat16* __restrict__ out, int total) {
    int i = blockIdx.x * blockDim.x + threadIdx.x;
    if (i >= total) return;
    const int K = 1 << LOGK;
    int r = i >> LOGK, c = i & (K-1);
    float v = in[i];
    __nv_bfloat16 hi, lo; split_bf(v, hi, lo);
    __nv_bfloat16* o = out + ((size_t)(3*r) << LOGK);
    o[c] = hi; o[K + c] = hi; o[2*K + c] = lo;
}

// ---------------- mma.sync bf16 GEMM: C[128-tile,128-tile] = A[.,Kp] @ W[.,Kp]^T ----------------
// EPI: 1 = +bias+resid -> fp32 out ; 2 = +bias+relu -> g_hiddens (split) ; 3 = +bias -> QKV scatter
#define MG_SMEM (2*32768)
template<int EPI>
__global__ __launch_bounds__(256) void k_mgemm(
    const __nv_bfloat16* __restrict__ A, const __nv_bfloat16* __restrict__ W,
    const float* __restrict__ bias, const float* __restrict__ resid,
    float* __restrict__ out, int Kp, int Nout)
{
    extern __shared__ char smem[];
    const int t = threadIdx.x, lane = t & 31, w = t >> 5;
    const int bm = blockIdx.x, bn = blockIdx.y;
    const uint32_t sbase = smem_u32(smem);
    const __nv_bfloat16* Ap = A + (size_t)bm * 128 * Kp;
    const __nv_bfloat16* Wp = W + (size_t)bn * 128 * Kp;
    const int nch = Kp >> 6;
    const int mrow = (w >> 2) * 64;   // 0 / 64
    const int ncol = (w & 3) * 32;    // 0,32,64,96

    float acc[4][4][4];
    #pragma unroll
    for (int a = 0; a < 4; a++)
        #pragma unroll
        for (int b = 0; b < 4; b++)
            #pragma unroll
            for (int c = 0; c < 4; c++) acc[a][b][c] = 0.f;

    // --- chunk loader: 128 A rows + 128 W rows, 64 bf16 (128B) each, XOR-swizzled ---
    auto load_chunk = [&](int ck, int buf) {
        int kc = ck * 64;
        #pragma unroll
        for (int i = 0; i < 8; i++) {
            int u = t + 256*i;
            int row_all = u >> 3, seg = u & 7;
            int isB = row_all >> 7;
            int row = row_all & 127;
            const __nv_bfloat16* src = (isB ? Wp : Ap) + (size_t)row * Kp + kc + seg*8;
            uint32_t dst = sbase + buf*32768 + isB*16384 + row*128 + ((seg ^ (row & 7)) * 16);
            asm volatile("cp.async.cg.shared.global [%0], [%1], 16;" :: "r"(dst), "l"(src));
        }
        asm volatile("cp.async.commit_group;" ::: "memory");
    };

    load_chunk(0, 0);
    for (int ck = 0; ck < nch; ck++) {
        if (ck + 1 < nch) {
            load_chunk(ck + 1, (ck + 1) & 1);
            asm volatile("cp.async.wait_group 1;" ::: "memory");
        } else {
            asm volatile("cp.async.wait_group 0;" ::: "memory");
        }
        __syncthreads();
        uint32_t Ab = sbase + (ck & 1)*32768;
        uint32_t Bb = Ab + 16384;
        #pragma unroll
        for (int s = 0; s < 4; s++) {
            int segsw = ((s*2 + (lane >> 4)) ^ (lane & 7)) * 16;
            uint32_t af[4][4];
            #pragma unroll
            for (int mt = 0; mt < 4; mt++) {
                uint32_t addr = Ab + (mrow + mt*16 + (lane & 15))*128 + segsw;
                asm volatile("ldmatrix.sync.aligned.m8n8.x4.shared.b16 {%0,%1,%2,%3}, [%4];"
                    : "=r"(af[mt][0]), "=r"(af[mt][1]), "=r"(af[mt][2]), "=r"(af[mt][3]) : "r"(addr));
            }
            uint32_t bf[4][2];
            #pragma unroll
            for (int half = 0; half < 2; half++) {
                uint32_t addr = Bb + (ncol + half*16 + (lane & 15))*128 + segsw;
                uint32_t r0, r1, r2, r3;
                asm volatile("ldmatrix.sync.aligned.m8n8.x4.shared.b16 {%0,%1,%2,%3}, [%4];"
                    : "=r"(r0), "=r"(r1), "=r"(r2), "=r"(r3) : "r"(addr));
                bf[half*2+0][0] = r0; bf[half*2+0][1] = r2;
                bf[half*2+1][0] = r1; bf[half*2+1][1] = r3;
            }
            #pragma unroll
            for (int mt = 0; mt < 4; mt++)
                #pragma unroll
                for (int nt = 0; nt < 4; nt++)
                    asm volatile(
                        "mma.sync.aligned.m16n8k16.row.col.f32.bf16.bf16.f32 "
                        "{%0,%1,%2,%3}, {%4,%5,%6,%7}, {%8,%9}, {%0,%1,%2,%3};"
                        : "+f"(acc[mt][nt][0]), "+f"(acc[mt][nt][1]),
                          "+f"(acc[mt][nt][2]), "+f"(acc[mt][nt][3])
                        : "r"(af[mt][0]), "r"(af[mt][1]), "r"(af[mt][2]), "r"(af[mt][3]),
                          "r"(bf[nt][0]), "r"(bf[nt][1]));
        }
        __syncthreads();
    }

    // --- epilogue straight from C fragments ---
    #pragma unroll
    for (int mt = 0; mt < 4; mt++) {
        int m0 = bm*128 + mrow + mt*16 + (lane >> 2);
        #pragma unroll
        for (int nt = 0; nt < 4; nt++) {
            int nl = ncol + nt*8 + 2*(lane & 3);   // local col in 0..127
            int ng = bn*128 + nl;                  // global col
            float bv0 = bias[ng], bv1 = bias[ng+1];
            #pragma unroll
            for (int hh = 0; hh < 2; hh++) {       // hh=0 -> row m0 (c0,c1); hh=1 -> m0+8 (c2,c3)
                int m = m0 + hh*8;
                float v0 = acc[mt][nt][hh*2+0] + bv0;
                float v1 = acc[mt][nt][hh*2+1] + bv1;
                if (EPI == 3) {
                    int h = nl >> 5, d = nl & 31;
                    float* dp = (bn == 0) ? g_q : (bn == 1) ? g_kbuf : g_vbuf;
                    *(float2*)(dp + ((size_t)((m >> 9)*HH + h)*NNODE + (m & 511))*DHD + d)
                        = make_float2(v0, v1);
                } else if (EPI == 2) {
                    v0 = fmaxf(v0, 0.f); v1 = fmaxf(v1, 0.f);
                    __nv_bfloat16 h0, l0, h1, l1;
                    split_bf(v0, h0, l0); split_bf(v1, h1, l1);
                    __nv_bfloat16* dst = g_hiddens + (size_t)m*768 + ng;
                    *(uint32_t*)(dst)       = pack_bf2(h0, h1);
                    *(uint32_t*)(dst + 256) = pack_bf2(l0, l1);
                    *(uint32_t*)(dst + 512) = pack_bf2(h0, h1);
                } else {
                    const float2 rv = *(const float2*)(resid + (size_t)m*Nout + ng);
                    *(float2*)(out + (size_t)m*Nout + ng) = make_float2(v0 + rv.x, v1 + rv.y);
                }
            }
        }
    }
}

// ---------------- attention (fp32, writes split output) ----------------
#define KT_S 516
#define S_S  516
#define QT_S 36
#define ATTN_SMEM ((32*KT_S + 512*32 + 32*S_S + 32*QT_S + 4096) * 4)

__global__ __launch_bounds__(256, 1) void k_attn() {
    extern __shared__ float sm[];
    float* Kt  = sm;
    float* Vs  = Kt + 32*KT_S;
    float* S   = Vs + 512*32;
    float* Qt  = S + 32*S_S;
    float* Red = Qt + 32*QT_S;
    int bh = blockIdx.x;
    int t  = threadIdx.x;
    const float* kb = g_kbuf + (size_t)bh * NNODE * DHD;
    const float* vb = g_vbuf + (size_t)bh * NNODE * DHD;
    const float* qb = g_q    + (size_t)bh * NNODE * DHD;
    int b = bh >> 2, h = bh & 3;

    for (int i = t; i < NNODE*8; i += 256) {
        int j  = i >> 3;
        int d4 = (i & 7) << 2;
        float4 kv = *(const float4*)(kb + j*DHD + d4);
        Kt[(d4+0)*KT_S + j] = kv.x;
        Kt[(d4+1)*KT_S + j] = kv.y;
        Kt[(d4+2)*KT_S + j] = kv.z;
        Kt[(d4+3)*KT_S + j] = kv.w;
        *(float4*)(Vs + j*DHD + d4) = *(const float4*)(vb + j*DHD + d4);
    }
    __syncthreads();

    const float sc = 0.17677669529663687f;
    for (int qt = 0; qt < 16; qt++) {
        for (int i = t; i < 1024; i += 256) {
            int qi = i >> 5, d = i & 31;
            Qt[d*QT_S + qi] = qb[(qt*32 + qi)*DHD + d];
        }
        __syncthreads();
        {
            int qg = t >> 6, jg = t & 63;
            float acc[8][8] = {};
            #pragma unroll 4
            for (int kk = 0; kk < 32; kk++) {
                float4 a0 = *(const float4*)(Qt + kk*QT_S + qg*8);
                float4 a1 = *(const float4*)(Qt + kk*QT_S + qg*8 + 4);
                float4 b0 = *(const float4*)(Kt + kk*KT_S + jg*8);
                float4 b1 = *(const float4*)(Kt + kk*KT_S + jg*8 + 4);
                float av[8] = {a0.x,a0.y,a0.z,a0.w,a1.x,a1.y,a1.z,a1.w};
                float bw[8] = {b0.x,b0.y,b0.z,b0.w,b1.x,b1.y,b1.z,b1.w};
                #pragma unroll
                for (int i = 0; i < 8; i++)
                    #pragma unroll
                    for (int j = 0; j < 8; j++)
                        acc[i][j] += av[i] * bw[j];
            }
            #pragma unroll
            for (int i = 0; i < 8; i++) {
                float* srow = S + (qg*8 + i)*S_S + jg*8;
                *(float4*)(srow)     = make_float4(acc[i][0]*sc, acc[i][1]*sc, acc[i][2]*sc, acc[i][3]*sc);
                *(float4*)(srow + 4) = make_float4(acc[i][4]*sc, acc[i][5]*sc, acc[i][6]*sc, acc[i][7]*sc);
            }
        }
        __syncthreads();
        {
            int w = t >> 5, lane = t & 31;
            for (int rr = 0; rr < 4; rr++) {
                int qi = w*4 + rr;
                float* row = S + qi*S_S;
                float vals[16];
                float mx = -1e30f;
                #pragma unroll
                for (int ii = 0; ii < 16; ii++) {
                    vals[ii] = row[lane + 32*ii];
                    mx = fmaxf(mx, vals[ii]);
                }
                #pragma unroll
                for (int o = 16; o > 0; o >>= 1) mx = fmaxf(mx, __shfl_xor_sync(0xffffffffu, mx, o));
                float sum = 0.f;
                #pragma unroll
                for (int ii = 0; ii < 16; ii++) { vals[ii] = __expf(vals[ii] - mx); sum += vals[ii]; }
                #pragma unroll
                for (int o = 16; o > 0; o >>= 1) sum += __shfl_xor_sync(0xffffffffu, sum, o);
                float inv = 1.f / sum;
                #pragma unroll
                for (int ii = 0; ii < 16; ii++) row[lane + 32*ii] = vals[ii] * inv;
            }
        }
        __syncthreads();
        {
            int js = t >> 6, r = t & 63, qg = r >> 3, dg = r & 7;
            float acc[4][4] = {};
            int j0 = js * 128;
            for (int j = j0; j < j0 + 128; j++) {
                float4 vv = *(const float4*)(Vs + j*32 + dg*4);
                #pragma unroll
                for (int i = 0; i < 4; i++) {
                    float p = S[(qg*4 + i)*S_S + j];
                    acc[i][0] += p*vv.x; acc[i][1] += p*vv.y;
                    acc[i][2] += p*vv.z; acc[i][3] += p*vv.w;
                }
            }
            #pragma unroll
            for (int i = 0; i < 4; i++)
                *(float4*)(Red + js*1024 + (qg*4 + i)*32 + dg*4) =
                    make_float4(acc[i][0], acc[i][1], acc[i][2], acc[i][3]);
        }
        __syncthreads();
        {
            int qi = t >> 3, d4 = (t & 7) << 2;
            float4 r0 = *(const float4*)(Red +        qi*32 + d4);
            float4 r1 = *(const float4*)(Red + 1024 + qi*32 + d4);
            float4 r2 = *(const float4*)(Red + 2048 + qi*32 + d4);
            float4 r3 = *(const float4*)(Red + 3072 + qi*32 + d4);
            float o4[4] = {r0.x+r1.x+r2.x+r3.x, r0.y+r1.y+r2.y+r3.y,
                           r0.z+r1.z+r2.z+r3.z, r0.w+r1.w+r2.w+r3.w};
            int nq = qt*32 + qi;
            // write split bf16 [hi|lo|hi] directly
            __nv_bfloat16 hi[4], lo[4];
            #pragma unroll
            for (int k = 0; k < 4; k++) split_bf(o4[k], hi[k], lo[k]);
            __nv_bfloat16* dst = g_obufs + ((size_t)(b*NNODE + nq))*384 + h*DHD + d4;
            *(uint32_t*)(dst)       = pack_bf2(hi[0], hi[1]);
            *(uint32_t*)(dst + 2)   = pack_bf2(hi[2], hi[3]);
            *(uint32_t*)(dst + 128) = pack_bf2(lo[0], lo[1]);
            *(uint32_t*)(dst + 130) = pack_bf2(lo[2], lo[3]);
            *(uint32_t*)(dst + 256) = pack_bf2(hi[0], hi[1]);
            *(uint32_t*)(dst + 258) = pack_bf2(hi[2], hi[3]);
        }
        __syncthreads();
    }
}

// ---------------- batchnorm stats / finalize / combine / final ----------------
__global__ void k_stats(const float* __restrict__ buf, int which) {
    int t = threadIdx.x;
    int c = t & 127, half = t >> 7;
    const float* p = buf + ((size_t)blockIdx.x*256 + half)*CC + c;
    float s = 0.f, s2 = 0.f;
    #pragma unroll 4
    for (int i = 0; i < 128; i++) {
        float v = p[(size_t)i*256];
        s += v; s2 += v*v;
    }
    __shared__ float sh[2][256];
    sh[0][t] = s; sh[1][t] = s2;
    __syncthreads();
    if (t < 128) {
        atomicAdd(&g_sums[which*256 + t],       sh[0][t] + sh[0][t+128]);
        atomicAdd(&g_sums[which*256 + 128 + t], sh[1][t] + sh[1][t+128]);
    }
}

__global__ void k_finalize(int which, const float* __restrict__ g, const float* __restrict__ b) {
    int c = threadIdx.x;
    float s  = g_sums[which*256 + c];
    float s2 = g_sums[which*256 + 128 + c];
    float m  = s / (float)NT;
    float v  = s2 / (float)NT - m*m;
    float scale = g[c] * rsqrtf(v + 1e-5f);
    g_scale[which*128 + c] = scale;
    g_shift[which*128 + c] = b[c] - m*scale;
}

__global__ void k_combine() {   // g_comb = bn1(hlocal)+bn2(hattn); also split -> g_combs
    int i = blockIdx.x * blockDim.x + threadIdx.x;
    int c = (i*4) & 127;
    int r = (i*4) >> 7;
    float4 a  = *(const float4*)(g_hlocal + (size_t)i*4);
    float4 bb = *(const float4*)(g_hattn + (size_t)i*4);
    float4 s1 = *(const float4*)(g_scale + c);
    float4 h1 = *(const float4*)(g_shift + c);
    float4 s2 = *(const float4*)(g_scale + 128 + c);
    float4 h2 = *(const float4*)(g_shift + 128 + c);
    float4 o;
    o.x = a.x*s1.x + h1.x + bb.x*s2.x + h2.x;
    o.y = a.y*s1.y + h1.y + bb.y*s2.y + h2.y;
    o.z = a.z*s1.z + h1.z + bb.z*s2.z + h2.z;
    o.w = a.w*s1.w + h1.w + bb.w*s2.w + h2.w;
    *(float4*)(g_comb + (size_t)i*4) = o;
    float vv[4] = {o.x, o.y, o.z, o.w};
    __nv_bfloat16 hi[4], lo[4];
    #pragma unroll
    for (int k = 0; k < 4; k++) split_bf(vv[k], hi[k], lo[k]);
    __nv_bfloat16* dst = g_combs + (size_t)r*384 + c;
    *(uint32_t*)(dst)       = pack_bf2(hi[0], hi[1]);
    *(uint32_t*)(dst + 2)   = pack_bf2(hi[2], hi[3]);
    *(uint32_t*)(dst + 128) = pack_bf2(lo[0], lo[1]);
    *(uint32_t*)(dst + 130) = pack_bf2(lo[2], lo[3]);
    *(uint32_t*)(dst + 256) = pack_bf2(hi[0], hi[1]);
    *(uint32_t*)(dst + 258) = pack_bf2(hi[2], hi[3]);
}

__global__ void k_final(float* __restrict__ out) {
    int i = blockIdx.x * blockDim.x + threadIdx.x;
    int c = (i*4) & 127;
    float4 a  = *(const float4*)(g_out2 + (size_t)i*4);
    float4 s3 = *(const float4*)(g_scale + 256 + c);
    float4 h3 = *(const float4*)(g_shift + 256 + c);
    float4 o;
    o.x = a.x*s3.x + h3.x;
    o.y = a.y*s3.y + h3.y;
    o.z = a.z*s3.z + h3.z;
    o.w = a.w*s3.w + h3.w;
    *(float4*)(out + (size_t)i*4) = o;
}

// ---------------- launch ----------------
extern "C" void kernel_launch(void* const* d_in, const int* in_sizes, int n_in,
                              void* d_out, int out_size) {
    const float* x   = (const float*)d_in[0];
    const int*   ei  = (const int*)  d_in[1];
    const float* Wc  = (const float*)d_in[2];
    const float* bc  = (const float*)d_in[3];
    const float* ipw = (const float*)d_in[4];
    const float* ipb = (const float*)d_in[5];
    const float* opw = (const float*)d_in[6];
    const float* opb = (const float*)d_in[7];
    const float* gn1 = (const float*)d_in[8];
    const float* bn1 = (const float*)d_in[9];
    const float* gn2 = (const float*)d_in[10];
    const float* bn2 = (const float*)d_in[11];
    const float* gn3 = (const float*)d_in[12];
    const float* bn3 = (const float*)d_in[13];
    const float* Wm1 = (const float*)d_in[14];
    const float* bm1 = (const float*)d_in[15];
    const float* Wm2 = (const float*)d_in[16];
    const float* bm2 = (const float*)d_in[17];
    const int* src = ei;
    const int* dst = ei + EE;

    void *p_hlocal, *p_hattn, *p_comb, *p_out2;
    void *p_xs, *p_aggs, *p_obufs, *p_combs, *p_hiddens;
    void *p_Wcs, *p_ipws, *p_opws, *p_Wm1s, *p_Wm2s;
    cudaGetSymbolAddress(&p_hlocal, g_hlocal);
    cudaGetSymbolAddress(&p_hattn,  g_hattn);
    cudaGetSymbolAddress(&p_comb,   g_comb);
    cudaGetSymbolAddress(&p_out2,   g_out2);
    cudaGetSymbolAddress(&p_xs,     g_xs);
    cudaGetSymbolAddress(&p_aggs,   g_aggs);
    cudaGetSymbolAddress(&p_obufs,  g_obufs);
    cudaGetSymbolAddress(&p_combs,  g_combs);
    cudaGetSymbolAddress(&p_hiddens,g_hiddens);
    cudaGetSymbolAddress(&p_Wcs,    g_Wcs);
    cudaGetSymbolAddress(&p_ipws,   g_ipws);
    cudaGetSymbolAddress(&p_opws,   g_opws);
    cudaGetSymbolAddress(&p_Wm1s,   g_Wm1s);
    cudaGetSymbolAddress(&p_Wm2s,   g_Wm2s);

    cudaFuncSetAttribute(k_attn, cudaFuncAttributeMaxDynamicSharedMemorySize, ATTN_SMEM);
    cudaFuncSetAttribute(k_mgemm<1>, cudaFuncAttributeMaxDynamicSharedMemorySize, MG_SMEM);
    cudaFuncSetAttribute(k_mgemm<2>, cudaFuncAttributeMaxDynamicSharedMemorySize, MG_SMEM);
    cudaFuncSetAttribute(k_mgemm<3>, cudaFuncAttributeMaxDynamicSharedMemorySize, MG_SMEM);

    k_zero<<<NT/256, 256>>>();
    k_deg<<<EE/256, 256>>>(dst);
    k_scan<<<1, 1024>>>();
    k_fill<<<EE/256, 256>>>(src, dst);

    // splits (weights: [hi|hi|lo], activations: [hi|lo|hi])
    k_splitw<7><<<(128*128+255)/256, 256>>>(Wc,  (__nv_bfloat16*)p_Wcs,  128*128);
    k_splitw<7><<<(384*128+255)/256, 256>>>(ipw, (__nv_bfloat16*)p_ipws, 384*128);
    k_splitw<7><<<(128*128+255)/256, 256>>>(opw, (__nv_bfloat16*)p_opws, 128*128);
    k_splitw<7><<<(256*128+255)/256, 256>>>(Wm1, (__nv_bfloat16*)p_Wm1s, 256*128);
    k_splitw<8><<<(128*256+255)/256, 256>>>(Wm2, (__nv_bfloat16*)p_Wm2s, 128*256);
    k_split<7><<<(NT*128+255)/256, 256>>>(x,    (__nv_bfloat16*)p_xs,   NT*128);

    k_agg<<<NT, 128>>>(x);

    // local: hlocal = aggs@Wcs^T + bc + x
    k_mgemm<1><<<dim3(NT/128, 1), 256, MG_SMEM>>>(
        (const __nv_bfloat16*)p_aggs, (const __nv_bfloat16*)p_Wcs, bc, x, (float*)p_hlocal, 384, 128);

    // qkv: scatter
    k_mgemm<3><<<dim3(NT/128, 3), 256, MG_SMEM>>>(
        (const __nv_bfloat16*)p_xs, (const __nv_bfloat16*)p_ipws, ipb, nullptr, nullptr, 384, 384);

    k_attn<<<BB*HH, 256, ATTN_SMEM>>>();

    // out_proj: hattn = obufs@opws^T + opb + x
    k_mgemm<1><<<dim3(NT/128, 1), 256, MG_SMEM>>>(
        (const __nv_bfloat16*)p_obufs, (const __nv_bfloat16*)p_opws, opb, x, (float*)p_hattn, 384, 128);

    k_stats<<<NT/256, 256>>>((const float*)p_hlocal, 0);
    k_stats<<<NT/256, 256>>>((const float*)p_hattn, 1);
    k_finalize<<<1, 128>>>(0, gn1, bn1);
    k_finalize<<<1, 128>>>(1, gn2, bn2);

    k_combine<<<NT*CC/4/256, 256>>>();

    // mlp1: hiddens(split) = relu(combs@Wm1s^T + bm1)
    k_mgemm<2><<<dim3(NT/128, 2), 256, MG_SMEM>>>(
        (const __nv_bfloat16*)p_combs, (const __nv_bfloat16*)p_Wm1s, bm1, nullptr, nullptr, 384, 256);

    // mlp2: out2 = hiddens@Wm2s^T + bm2 + comb
    k_mgemm<1><<<dim3(NT/128, 1), 256, MG_SMEM>>>(
        (const __nv_bfloat16*)p_hiddens, (const __nv_bfloat16*)p_Wm2s, bm2, (const float*)p_comb, (float*)p_out2, 768, 128);

    k_stats<<<NT/256, 256>>>((const float*)p_out2, 2);
    k_finalize<<<1, 128>>>(2, gn3, bn3);
    k_final<<<NT*CC/4/256, 256>>>((float*)d_out);
}

// round 5
// speedup vs baseline: 1.7403x; 1.4566x over previous
#include <cuda_runtime.h>
#include <cuda_bf16.h>
#include <math.h>
#include <stdint.h>

#define NT  32768
#define CC  128
#define BB  64
#define NNODE 512
#define HH  4
#define DHD 32
#define EE  524288

// ---------------- scratch (device globals; no allocation allowed) ----------------
__device__ int   g_deg[NT];
__device__ int   g_off[NT+1];
__device__ int   g_cur[NT];
__device__ int   g_nbr[EE];
__device__ float g_hlocal[NT*CC];
__device__ float g_hattn[NT*CC];
__device__ float g_comb[NT*CC];
__device__ float g_out2[NT*CC];
__device__ float g_sums[3*2*CC];
__device__ float g_scale[3*CC];
__device__ float g_shift[3*CC];

// bf16 split buffers
__device__ __nv_bfloat16 g_xs[NT*384];       // [hi|lo|hi]
__device__ __nv_bfloat16 g_aggs[NT*384];
__device__ __nv_bfloat16 g_obufs[NT*384];
__device__ __nv_bfloat16 g_combs[NT*384];
__device__ __nv_bfloat16 g_hiddens[NT*768];
__device__ __nv_bfloat16 g_Wcs[128*384];     // [hi|hi|lo]
__device__ __nv_bfloat16 g_ipws[384*384];
__device__ __nv_bfloat16 g_opws[128*384];
__device__ __nv_bfloat16 g_Wm1s[256*384];
__device__ __nv_bfloat16 g_Wm2s[128*768];
// attention operands: [bh][node][hi(32)|lo(32)] bf16
__device__ __nv_bfloat16 g_qs[BB*HH*NNODE*64];
__device__ __nv_bfloat16 g_ks[BB*HH*NNODE*64];
__device__ __nv_bfloat16 g_vs[BB*HH*NNODE*64];

// ---------------- helpers ----------------
__device__ __forceinline__ uint32_t smem_u32(const void* p) {
    uint32_t a;
    asm("{ .reg .u64 t; cvta.to.shared.u64 t, %1; cvt.u32.u64 %0, t; }" : "=r"(a) : "l"(p));
    return a;
}
__device__ __forceinline__ uint32_t pack_bf2(__nv_bfloat16 a, __nv_bfloat16 b) {
    return (uint32_t)__bfloat16_as_ushort(a) | ((uint32_t)__bfloat16_as_ushort(b) << 16);
}
__device__ __forceinline__ void split_bf(float v, __nv_bfloat16& hi, __nv_bfloat16& lo) {
    hi = __float2bfloat16(v);
    lo = __float2bfloat16(v - __bfloat162float(hi));
}
__device__ __forceinline__ void ldmx4(uint32_t* r, uint32_t addr) {
    asm volatile("ldmatrix.sync.aligned.m8n8.x4.shared.b16 {%0,%1,%2,%3}, [%4];"
        : "=r"(r[0]), "=r"(r[1]), "=r"(r[2]), "=r"(r[3]) : "r"(addr));
}
__device__ __forceinline__ void mma_bf(float* c, const uint32_t* a, uint32_t b0, uint32_t b1) {
    asm volatile("mma.sync.aligned.m16n8k16.row.col.f32.bf16.bf16.f32 "
        "{%0,%1,%2,%3}, {%4,%5,%6,%7}, {%8,%9}, {%0,%1,%2,%3};"
        : "+f"(c[0]), "+f"(c[1]), "+f"(c[2]), "+f"(c[3])
        : "r"(a[0]), "r"(a[1]), "r"(a[2]), "r"(a[3]), "r"(b0), "r"(b1));
}

// ---------------- CSR build ----------------
__global__ void k_zero() {
    int i = blockIdx.x * blockDim.x + threadIdx.x;
    if (i < NT) g_deg[i] = 0;
    if (i < 3*2*CC) g_sums[i] = 0.f;
}
__global__ void k_deg(const int* __restrict__ dst) {
    int i = blockIdx.x * blockDim.x + threadIdx.x;
    if (i < EE) atomicAdd(&g_deg[dst[i]], 1);
}
__global__ void k_scan() {
    __shared__ int ssum[1024];
    int t = threadIdx.x;
    int base = t * 32;
    int s = 0;
    #pragma unroll
    for (int i = 0; i < 32; i++) s += g_deg[base + i];
    ssum[t] = s;
    __syncthreads();
    for (int off = 1; off < 1024; off <<= 1) {
        int tmp = (t >= off) ? ssum[t - off] : 0;
        __syncthreads();
        ssum[t] += tmp;
        __syncthreads();
    }
    int run = ssum[t] - s;
    #pragma unroll
    for (int i = 0; i < 32; i++) {
        g_off[base + i] = run;
        g_cur[base + i] = run;
        run += g_deg[base + i];
    }
    if (t == 1023) g_off[NT] = run;
}
__global__ void k_fill(const int* __restrict__ src, const int* __restrict__ dst) {
    int i = blockIdx.x * blockDim.x + threadIdx.x;
    if (i < EE) {
        int p = atomicAdd(&g_cur[dst[i]], 1);
        g_nbr[p] = src[i];
    }
}

// ---------------- mean aggregation (gather) -> split bf16 ----------------
__global__ void k_agg(const float* __restrict__ x) {
    __shared__ int snbr[128];
    int n = blockIdx.x, c = threadIdx.x;
    int s0 = g_off[n], s1 = g_off[n+1];
    float acc = 0.f;
    for (int j0 = s0; j0 < s1; j0 += 128) {
        int m = min(128, s1 - j0);
        __syncthreads();
        if (c < m) snbr[c] = g_nbr[j0 + c];
        __syncthreads();
        for (int jj = 0; jj < m; jj++) acc += x[snbr[jj]*CC + c];
    }
    float d = (float)(s1 - s0);
    float v = acc / fmaxf(d, 1.f);
    __nv_bfloat16 hi, lo; split_bf(v, hi, lo);
    size_t base = (size_t)n * 384;
    g_aggs[base + c] = hi;
    g_aggs[base + 128 + c] = lo;
    g_aggs[base + 256 + c] = hi;
}

// ---------------- split kernels ----------------
template<int LOGK>
__global__ void k_split(const float* __restrict__ in, __nv_bfloat16* __restrict__ out, int total) {
    int i = blockIdx.x * blockDim.x + threadIdx.x;
    if (i >= total) return;
    const int K = 1 << LOGK;
    int r = i >> LOGK, c = i & (K-1);
    float v = in[i];
    __nv_bfloat16 hi, lo; split_bf(v, hi, lo);
    __nv_bfloat16* o = out + ((size_t)(3*r) << LOGK);
    o[c] = hi; o[K + c] = lo; o[2*K + c] = hi;
}
template<int LOGK>
__global__ void k_splitw(const float* __restrict__ in, __nv_bfloat16* __restrict__ out, int total) {
    int i = blockIdx.x * blockDim.x + threadIdx.x;
    if (i >= total) return;
    const int K = 1 << LOGK;
    int r = i >> LOGK, c = i & (K-1);
    float v = in[i];
    __nv_bfloat16 hi, lo; split_bf(v, hi, lo);
    __nv_bfloat16* o = out + ((size_t)(3*r) << LOGK);
    o[c] = hi; o[K + c] = hi; o[2*K + c] = lo;
}

// ---------------- mma.sync bf16 GEMM ----------------
// EPI: 1 = +bias+resid -> fp32 out ; 2 = +bias+relu -> g_hiddens (split) ; 3 = +bias -> QKV bf16 split
#define MG_SMEM (2*32768)
template<int EPI>
__global__ __launch_bounds__(256) void k_mgemm(
    const __nv_bfloat16* __restrict__ A, const __nv_bfloat16* __restrict__ W,
    const float* __restrict__ bias, const float* __restrict__ resid,
    float* __restrict__ out, int Kp, int Nout)
{
    extern __shared__ char smem[];
    const int t = threadIdx.x, lane = t & 31, w = t >> 5;
    const int bm = blockIdx.x, bn = blockIdx.y;
    const uint32_t sbase = smem_u32(smem);
    const __nv_bfloat16* Ap = A + (size_t)bm * 128 * Kp;
    const __nv_bfloat16* Wp = W + (size_t)bn * 128 * Kp;
    const int nch = Kp >> 6;
    const int mrow = (w >> 2) * 64;
    const int ncol = (w & 3) * 32;

    float acc[4][4][4];
    #pragma unroll
    for (int a = 0; a < 4; a++)
        #pragma unroll
        for (int b = 0; b < 4; b++)
            #pragma unroll
            for (int c = 0; c < 4; c++) acc[a][b][c] = 0.f;

    auto load_chunk = [&](int ck, int buf) {
        int kc = ck * 64;
        #pragma unroll
        for (int i = 0; i < 8; i++) {
            int u = t + 256*i;
            int row_all = u >> 3, seg = u & 7;
            int isB = row_all >> 7;
            int row = row_all & 127;
            const __nv_bfloat16* src = (isB ? Wp : Ap) + (size_t)row * Kp + kc + seg*8;
            uint32_t dst = sbase + buf*32768 + isB*16384 + row*128 + ((seg ^ (row & 7)) * 16);
            asm volatile("cp.async.cg.shared.global [%0], [%1], 16;" :: "r"(dst), "l"(src));
        }
        asm volatile("cp.async.commit_group;" ::: "memory");
    };

    load_chunk(0, 0);
    for (int ck = 0; ck < nch; ck++) {
        if (ck + 1 < nch) {
            load_chunk(ck + 1, (ck + 1) & 1);
            asm volatile("cp.async.wait_group 1;" ::: "memory");
        } else {
            asm volatile("cp.async.wait_group 0;" ::: "memory");
        }
        __syncthreads();
        uint32_t Ab = sbase + (ck & 1)*32768;
        uint32_t Bb = Ab + 16384;
        #pragma unroll
        for (int s = 0; s < 4; s++) {
            int segsw = ((s*2 + (lane >> 4)) ^ (lane & 7)) * 16;
            uint32_t af[4][4];
            #pragma unroll
            for (int mt = 0; mt < 4; mt++) {
                uint32_t addr = Ab + (mrow + mt*16 + (lane & 15))*128 + segsw;
                ldmx4(af[mt], addr);
            }
            uint32_t bf[4][2];
            #pragma unroll
            for (int half = 0; half < 2; half++) {
                uint32_t addr = Bb + (ncol + half*16 + (lane & 15))*128 + segsw;
                uint32_t r4[4];
                ldmx4(r4, addr);
                bf[half*2+0][0] = r4[0]; bf[half*2+0][1] = r4[2];
                bf[half*2+1][0] = r4[1]; bf[half*2+1][1] = r4[3];
            }
            #pragma unroll
            for (int mt = 0; mt < 4; mt++)
                #pragma unroll
                for (int nt = 0; nt < 4; nt++)
                    mma_bf(acc[mt][nt], af[mt], bf[nt][0], bf[nt][1]);
        }
        __syncthreads();
    }

    #pragma unroll
    for (int mt = 0; mt < 4; mt++) {
        int m0 = bm*128 + mrow + mt*16 + (lane >> 2);
        #pragma unroll
        for (int nt = 0; nt < 4; nt++) {
            int nl = ncol + nt*8 + 2*(lane & 3);
            int ng = bn*128 + nl;
            float bv0 = bias[ng], bv1 = bias[ng+1];
            #pragma unroll
            for (int hh = 0; hh < 2; hh++) {
                int m = m0 + hh*8;
                float v0 = acc[mt][nt][hh*2+0] + bv0;
                float v1 = acc[mt][nt][hh*2+1] + bv1;
                if (EPI == 3) {
                    int h = nl >> 5, d = nl & 31;
                    __nv_bfloat16* dp = (bn == 0) ? g_qs : (bn == 1) ? g_ks : g_vs;
                    int bh = (m >> 9)*HH + h;
                    __nv_bfloat16 h0, l0, h1, l1;
                    split_bf(v0, h0, l0); split_bf(v1, h1, l1);
                    __nv_bfloat16* dst = dp + ((size_t)bh*NNODE + (m & 511))*64 + d;
                    *(uint32_t*)(dst)      = pack_bf2(h0, h1);
                    *(uint32_t*)(dst + 32) = pack_bf2(l0, l1);
                } else if (EPI == 2) {
                    v0 = fmaxf(v0, 0.f); v1 = fmaxf(v1, 0.f);
                    __nv_bfloat16 h0, l0, h1, l1;
                    split_bf(v0, h0, l0); split_bf(v1, h1, l1);
                    __nv_bfloat16* dst = g_hiddens + (size_t)m*768 + ng;
                    *(uint32_t*)(dst)       = pack_bf2(h0, h1);
                    *(uint32_t*)(dst + 256) = pack_bf2(l0, l1);
                    *(uint32_t*)(dst + 512) = pack_bf2(h0, h1);
                } else {
                    const float2 rv = *(const float2*)(resid + (size_t)m*Nout + ng);
                    *(float2*)(out + (size_t)m*Nout + ng) = make_float2(v0 + rv.x, v1 + rv.y);
                }
            }
        }
    }
}

// ---------------- flash attention: mma.sync bf16 with split-3 accuracy ----------------
// block per (b,h); 256 threads = 8 warps; warp owns 64 q-rows.
// smem: Q[512][64] (64KB) | K[512][64] (64KB) | Vt[64][512] (64KB)
#define FA_SMEM (3*65536)
__global__ __launch_bounds__(256, 1) void k_fattn() {
    extern __shared__ char sm2[];
    const uint32_t sb = smem_u32(sm2);
    const uint32_t Qb = sb, Kb = sb + 65536, Vb = sb + 131072;
    const int bh = blockIdx.x, t = threadIdx.x, lane = t & 31, w = t >> 5;
    const __nv_bfloat16* qg = g_qs + (size_t)bh * NNODE * 64;
    const __nv_bfloat16* kg = g_ks + (size_t)bh * NNODE * 64;
    const __nv_bfloat16* vg = g_vs + (size_t)bh * NNODE * 64;

    // load Q, K (row-swizzled, same layout as GEMM tiles)
    for (int i = t; i < 4096; i += 256) {
        int r = i >> 3, s = i & 7;
        uint32_t off = (uint32_t)(r*128 + ((s ^ (r & 7)) * 16));
        *(float4*)(sm2 + off)          = *(const float4*)(qg + r*64 + s*8);
        *(float4*)(sm2 + 65536 + off)  = *(const float4*)(kg + r*64 + s*8);
    }
    // V transposed into Vt[64 rows (hi d 0-31 | lo d 0-31)][512 j], swizzled per row
    for (int i = t; i < 4096; i += 256) {
        int j = i & 511, s = i >> 9;
        float4 v4 = *(const float4*)(vg + j*64 + s*8);
        const __nv_bfloat16* pv = (const __nv_bfloat16*)&v4;
        #pragma unroll
        for (int k = 0; k < 8; k++) {
            int d = s*8 + k;
            *(__nv_bfloat16*)(sm2 + 131072 + d*1024 + (((j >> 3) ^ (d & 7)) * 16) + (j & 7)*2) = pv[k];
        }
    }
    __syncthreads();

    const int q0 = w * 64;
    // resident Q-hi fragments
    uint32_t aqh[4][2][4];
    #pragma unroll
    for (int mt = 0; mt < 4; mt++)
        #pragma unroll
        for (int kc = 0; kc < 2; kc++) {
            int row = q0 + mt*16 + (lane & 15);
            ldmx4(aqh[mt][kc], Qb + row*128 + (((kc*2 + (lane >> 4)) ^ (row & 7)) * 16));
        }

    float of[4][4][4];
    #pragma unroll
    for (int a = 0; a < 4; a++)
        #pragma unroll
        for (int b = 0; b < 4; b++)
            #pragma unroll
            for (int c = 0; c < 4; c++) of[a][b][c] = 0.f;
    float mrow[4][2], lrow[4][2];
    #pragma unroll
    for (int a = 0; a < 4; a++) { mrow[a][0] = -1e30f; mrow[a][1] = -1e30f; lrow[a][0] = 0.f; lrow[a][1] = 0.f; }

    const float sc = 0.17677669529663687f; // 1/sqrt(32)

    for (int jb = 0; jb < 32; jb++) {
        const int j0 = jb * 16;
        // K B-fragments: bk[kc][ntile][2]; kc 0,1 = hi halves; 2,3 = lo halves
        uint32_t bk[4][2][2];
        #pragma unroll
        for (int kc = 0; kc < 4; kc++) {
            int row = j0 + (lane & 15);
            uint32_t r4[4];
            ldmx4(r4, Kb + row*128 + (((kc*2 + (lane >> 4)) ^ (row & 7)) * 16));
            bk[kc][0][0] = r4[0]; bk[kc][0][1] = r4[2];
            bk[kc][1][0] = r4[1]; bk[kc][1][1] = r4[3];
        }
        // scores: 3-term split (Qhi·Khi + Qlo·Khi + Qhi·Klo)
        float c[4][2][4];
        #pragma unroll
        for (int a = 0; a < 4; a++)
            #pragma unroll
            for (int b = 0; b < 2; b++)
                #pragma unroll
                for (int e = 0; e < 4; e++) c[a][b][e] = 0.f;
        #pragma unroll
        for (int mt = 0; mt < 4; mt++) {
            uint32_t aql[2][4];
            #pragma unroll
            for (int kc = 0; kc < 2; kc++) {
                int row = q0 + mt*16 + (lane & 15);
                ldmx4(aql[kc], Qb + row*128 + ((((kc + 2)*2 + (lane >> 4)) ^ (row & 7)) * 16));
            }
            #pragma unroll
            for (int nt = 0; nt < 2; nt++) {
                mma_bf(c[mt][nt], aqh[mt][0], bk[0][nt][0], bk[0][nt][1]);
                mma_bf(c[mt][nt], aqh[mt][1], bk[1][nt][0], bk[1][nt][1]);
                mma_bf(c[mt][nt], aql[0],     bk[0][nt][0], bk[0][nt][1]);
                mma_bf(c[mt][nt], aql[1],     bk[1][nt][0], bk[1][nt][1]);
                mma_bf(c[mt][nt], aqh[mt][0], bk[2][nt][0], bk[2][nt][1]);
                mma_bf(c[mt][nt], aqh[mt][1], bk[3][nt][0], bk[3][nt][1]);
            }
        }
        // online softmax update
        #pragma unroll
        for (int mt = 0; mt < 4; mt++)
            #pragma unroll
            for (int h = 0; h < 2; h++) {
                float s0 = c[mt][0][h*2]*sc, s1 = c[mt][0][h*2+1]*sc;
                float s2 = c[mt][1][h*2]*sc, s3 = c[mt][1][h*2+1]*sc;
                float mx = fmaxf(fmaxf(s0, s1), fmaxf(s2, s3));
                mx = fmaxf(mx, __shfl_xor_sync(0xffffffffu, mx, 1));
                mx = fmaxf(mx, __shfl_xor_sync(0xffffffffu, mx, 2));
                float mnew = fmaxf(mrow[mt][h], mx);
                float fac = __expf(mrow[mt][h] - mnew);
                mrow[mt][h] = mnew;
                float p0 = __expf(s0 - mnew), p1 = __expf(s1 - mnew);
                float p2 = __expf(s2 - mnew), p3 = __expf(s3 - mnew);
                c[mt][0][h*2] = p0; c[mt][0][h*2+1] = p1;
                c[mt][1][h*2] = p2; c[mt][1][h*2+1] = p3;
                float rs = p0 + p1 + p2 + p3;
                rs += __shfl_xor_sync(0xffffffffu, rs, 1);
                rs += __shfl_xor_sync(0xffffffffu, rs, 2);
                lrow[mt][h] = lrow[mt][h]*fac + rs;
                #pragma unroll
                for (int nt = 0; nt < 4; nt++) { of[mt][nt][h*2] *= fac; of[mt][nt][h*2+1] *= fac; }
            }
        // P fragments (A operand for PV): repack C frags, split hi/lo
        uint32_t pah[4][4], pal[4][4];
        #pragma unroll
        for (int mt = 0; mt < 4; mt++) {
            float x0 = c[mt][0][0], y0 = c[mt][0][1];
            float x1 = c[mt][0][2], y1 = c[mt][0][3];
            float x2 = c[mt][1][0], y2 = c[mt][1][1];
            float x3 = c[mt][1][2], y3 = c[mt][1][3];
            __nv_bfloat16 hx, lx, hy, ly;
            split_bf(x0, hx, lx); split_bf(y0, hy, ly);
            pah[mt][0] = pack_bf2(hx, hy); pal[mt][0] = pack_bf2(lx, ly);
            split_bf(x1, hx, lx); split_bf(y1, hy, ly);
            pah[mt][1] = pack_bf2(hx, hy); pal[mt][1] = pack_bf2(lx, ly);
            split_bf(x2, hx, lx); split_bf(y2, hy, ly);
            pah[mt][2] = pack_bf2(hx, hy); pal[mt][2] = pack_bf2(lx, ly);
            split_bf(x3, hx, lx); split_bf(y3, hy, ly);
            pah[mt][3] = pack_bf2(hx, hy); pal[mt][3] = pack_bf2(lx, ly);
        }
        // V B-fragments for this j-chunk: bvh/bvl [d-ntile 0..3][2]
        uint32_t bvh[4][2], bvl[4][2];
        #pragma unroll
        for (int dh = 0; dh < 2; dh++) {
            int rowh = dh*16 + (lane & 15);
            uint32_t r4[4];
            ldmx4(r4, Vb + rowh*1024 + (((((j0 >> 3) + (lane >> 4)) ^ (rowh & 7))) * 16));
            bvh[dh*2+0][0] = r4[0]; bvh[dh*2+0][1] = r4[2];
            bvh[dh*2+1][0] = r4[1]; bvh[dh*2+1][1] = r4[3];
            int rowl = rowh + 32;
            ldmx4(r4, Vb + rowl*1024 + (((((j0 >> 3) + (lane >> 4)) ^ (rowl & 7))) * 16));
            bvl[dh*2+0][0] = r4[0]; bvl[dh*2+0][1] = r4[2];
            bvl[dh*2+1][0] = r4[1]; bvl[dh*2+1][1] = r4[3];
        }
        // PV: 3-term (Phi·Vhi + Plo·Vhi + Phi·Vlo)
        #pragma unroll
        for (int mt = 0; mt < 4; mt++)
            #pragma unroll
            for (int nt = 0; nt < 4; nt++) {
                mma_bf(of[mt][nt], pah[mt], bvh[nt][0], bvh[nt][1]);
                mma_bf(of[mt][nt], pal[mt], bvh[nt][0], bvh[nt][1]);
                mma_bf(of[mt][nt], pah[mt], bvl[nt][0], bvl[nt][1]);
            }
    }

    // epilogue: normalize, split, write g_obufs [hi|lo|hi]
    const int b = bh >> 2, h4 = bh & 3;
    #pragma unroll
    for (int mt = 0; mt < 4; mt++)
        #pragma unroll
        for (int h = 0; h < 2; h++) {
            float inv = 1.f / lrow[mt][h];
            int q = q0 + mt*16 + (lane >> 2) + h*8;
            __nv_bfloat16* base = g_obufs + ((size_t)(b*NNODE + q))*384 + h4*DHD;
            #pragma unroll
            for (int nt = 0; nt < 4; nt++) {
                int d = nt*8 + 2*(lane & 3);
                float v0 = of[mt][nt][h*2]   * inv;
                float v1 = of[mt][nt][h*2+1] * inv;
                __nv_bfloat16 h0, l0, h1, l1;
                split_bf(v0, h0, l0); split_bf(v1, h1, l1);
                *(uint32_t*)(base + d)       = pack_bf2(h0, h1);
                *(uint32_t*)(base + 128 + d) = pack_bf2(l0, l1);
                *(uint32_t*)(base + 256 + d) = pack_bf2(h0, h1);
            }
        }
}

// ---------------- batchnorm stats / finalize / combine / final ----------------
__global__ void k_stats(const float* __restrict__ buf, int which) {
    int t = threadIdx.x;
    int c = t & 127, half = t >> 7;
    const float* p = buf + ((size_t)blockIdx.x*256 + half)*CC + c;
    float s = 0.f, s2 = 0.f;
    #pragma unroll 4
    for (int i = 0; i < 128; i++) {
        float v = p[(size_t)i*256];
        s += v; s2 += v*v;
    }
    __shared__ float sh[2][256];
    sh[0][t] = s; sh[1][t] = s2;
    __syncthreads();
    if (t < 128) {
        atomicAdd(&g_sums[which*256 + t],       sh[0][t] + sh[0][t+128]);
        atomicAdd(&g_sums[which*256 + 128 + t], sh[1][t] + sh[1][t+128]);
    }
}

__global__ void k_finalize(int which, const float* __restrict__ g, const float* __restrict__ b) {
    int c = threadIdx.x;
    float s  = g_sums[which*256 + c];
    float s2 = g_sums[which*256 + 128 + c];
    float m  = s / (float)NT;
    float v  = s2 / (float)NT - m*m;
    float scale = g[c] * rsqrtf(v + 1e-5f);
    g_scale[which*128 + c] = scale;
    g_shift[which*128 + c] = b[c] - m*scale;
}

__global__ void k_combine() {
    int i = blockIdx.x * blockDim.x + threadIdx.x;
    int c = (i*4) & 127;
    int r = (i*4) >> 7;
    float4 a  = *(const float4*)(g_hlocal + (size_t)i*4);
    float4 bb = *(const float4*)(g_hattn + (size_t)i*4);
    float4 s1 = *(const float4*)(g_scale + c);
    float4 h1 = *(const float4*)(g_shift + c);
    float4 s2 = *(const float4*)(g_scale + 128 + c);
    float4 h2 = *(const float4*)(g_shift + 128 + c);
    float4 o;
    o.x = a.x*s1.x + h1.x + bb.x*s2.x + h2.x;
    o.y = a.y*s1.y + h1.y + bb.y*s2.y + h2.y;
    o.z = a.z*s1.z + h1.z + bb.z*s2.z + h2.z;
    o.w = a.w*s1.w + h1.w + bb.w*s2.w + h2.w;
    *(float4*)(g_comb + (size_t)i*4) = o;
    float vv[4] = {o.x, o.y, o.z, o.w};
    __nv_bfloat16 hi[4], lo[4];
    #pragma unroll
    for (int k = 0; k < 4; k++) split_bf(vv[k], hi[k], lo[k]);
    __nv_bfloat16* dst = g_combs + (size_t)r*384 + c;
    *(uint32_t*)(dst)       = pack_bf2(hi[0], hi[1]);
    *(uint32_t*)(dst + 2)   = pack_bf2(hi[2], hi[3]);
    *(uint32_t*)(dst + 128) = pack_bf2(lo[0], lo[1]);
    *(uint32_t*)(dst + 130) = pack_bf2(lo[2], lo[3]);
    *(uint32_t*)(dst + 256) = pack_bf2(hi[0], hi[1]);
    *(uint32_t*)(dst + 258) = pack_bf2(hi[2], hi[3]);
}

__global__ void k_final(float* __restrict__ out) {
    int i = blockIdx.x * blockDim.x + threadIdx.x;
    int c = (i*4) & 127;
    float4 a  = *(const float4*)(g_out2 + (size_t)i*4);
    float4 s3 = *(const float4*)(g_scale + 256 + c);
    float4 h3 = *(const float4*)(g_shift + 256 + c);
    float4 o;
    o.x = a.x*s3.x + h3.x;
    o.y = a.y*s3.y + h3.y;
    o.z = a.z*s3.z + h3.z;
    o.w = a.w*s3.w + h3.w;
    *(float4*)(out + (size_t)i*4) = o;
}

// ---------------- launch ----------------
extern "C" void kernel_launch(void* const* d_in, const int* in_sizes, int n_in,
                              void* d_out, int out_size) {
    const float* x   = (const float*)d_in[0];
    const int*   ei  = (const int*)  d_in[1];
    const float* Wc  = (const float*)d_in[2];
    const float* bc  = (const float*)d_in[3];
    const float* ipw = (const float*)d_in[4];
    const float* ipb = (const float*)d_in[5];
    const float* opw = (const float*)d_in[6];
    const float* opb = (const float*)d_in[7];
    const float* gn1 = (const float*)d_in[8];
    const float* bn1 = (const float*)d_in[9];
    const float* gn2 = (const float*)d_in[10];
    const float* bn2 = (const float*)d_in[11];
    const float* gn3 = (const float*)d_in[12];
    const float* bn3 = (const float*)d_in[13];
    const float* Wm1 = (const float*)d_in[14];
    const float* bm1 = (const float*)d_in[15];
    const float* Wm2 = (const float*)d_in[16];
    const float* bm2 = (const float*)d_in[17];
    const int* src = ei;
    const int* dst = ei + EE;

    void *p_hlocal, *p_hattn, *p_comb, *p_out2;
    void *p_xs, *p_aggs, *p_obufs, *p_combs, *p_hiddens;
    void *p_Wcs, *p_ipws, *p_opws, *p_Wm1s, *p_Wm2s;
    cudaGetSymbolAddress(&p_hlocal, g_hlocal);
    cudaGetSymbolAddress(&p_hattn,  g_hattn);
    cudaGetSymbolAddress(&p_comb,   g_comb);
    cudaGetSymbolAddress(&p_out2,   g_out2);
    cudaGetSymbolAddress(&p_xs,     g_xs);
    cudaGetSymbolAddress(&p_aggs,   g_aggs);
    cudaGetSymbolAddress(&p_obufs,  g_obufs);
    cudaGetSymbolAddress(&p_combs,  g_combs);
    cudaGetSymbolAddress(&p_hiddens,g_hiddens);
    cudaGetSymbolAddress(&p_Wcs,    g_Wcs);
    cudaGetSymbolAddress(&p_ipws,   g_ipws);
    cudaGetSymbolAddress(&p_opws,   g_opws);
    cudaGetSymbolAddress(&p_Wm1s,   g_Wm1s);
    cudaGetSymbolAddress(&p_Wm2s,   g_Wm2s);

    cudaFuncSetAttribute(k_fattn, cudaFuncAttributeMaxDynamicSharedMemorySize, FA_SMEM);
    cudaFuncSetAttribute(k_mgemm<1>, cudaFuncAttributeMaxDynamicSharedMemorySize, MG_SMEM);
    cudaFuncSetAttribute(k_mgemm<2>, cudaFuncAttributeMaxDynamicSharedMemorySize, MG_SMEM);
    cudaFuncSetAttribute(k_mgemm<3>, cudaFuncAttributeMaxDynamicSharedMemorySize, MG_SMEM);

    k_zero<<<NT/256, 256>>>();
    k_deg<<<EE/256, 256>>>(dst);
    k_scan<<<1, 1024>>>();
    k_fill<<<EE/256, 256>>>(src, dst);

    k_splitw<7><<<(128*128+255)/256, 256>>>(Wc,  (__nv_bfloat16*)p_Wcs,  128*128);
    k_splitw<7><<<(384*128+255)/256, 256>>>(ipw, (__nv_bfloat16*)p_ipws, 384*128);
    k_splitw<7><<<(128*128+255)/256, 256>>>(opw, (__nv_bfloat16*)p_opws, 128*128);
    k_splitw<7><<<(256*128+255)/256, 256>>>(Wm1, (__nv_bfloat16*)p_Wm1s, 256*128);
    k_splitw<8><<<(128*256+255)/256, 256>>>(Wm2, (__nv_bfloat16*)p_Wm2s, 128*256);
    k_split<7><<<(NT*128+255)/256, 256>>>(x,    (__nv_bfloat16*)p_xs,   NT*128);

    k_agg<<<NT, 128>>>(x);

    // local: hlocal = aggs@Wcs^T + bc + x
    k_mgemm<1><<<dim3(NT/128, 1), 256, MG_SMEM>>>(
        (const __nv_bfloat16*)p_aggs, (const __nv_bfloat16*)p_Wcs, bc, x, (float*)p_hlocal, 384, 128);

    // qkv -> bf16 split scatter
    k_mgemm<3><<<dim3(NT/128, 3), 256, MG_SMEM>>>(
        (const __nv_bfloat16*)p_xs, (const __nv_bfloat16*)p_ipws, ipb, nullptr, nullptr, 384, 384);

    k_fattn<<<BB*HH, 256, FA_SMEM>>>();

    // out_proj: hattn = obufs@opws^T + opb + x
    k_mgemm<1><<<dim3(NT/128, 1), 256, MG_SMEM>>>(
        (const __nv_bfloat16*)p_obufs, (const __nv_bfloat16*)p_opws, opb, x, (float*)p_hattn, 384, 128);

    k_stats<<<NT/256, 256>>>((const float*)p_hlocal, 0);
    k_stats<<<NT/256, 256>>>((const float*)p_hattn, 1);
    k_finalize<<<1, 128>>>(0, gn1, bn1);
    k_finalize<<<1, 128>>>(1, gn2, bn2);

    k_combine<<<NT*CC/4/256, 256>>>();

    // mlp1: hiddens(split) = relu(combs@Wm1s^T + bm1)
    k_mgemm<2><<<dim3(NT/128, 2), 256, MG_SMEM>>>(
        (const __nv_bfloat16*)p_combs, (const __nv_bfloat16*)p_Wm1s, bm1, nullptr, nullptr, 384, 256);

    // mlp2: out2 = hiddens@Wm2s^T + bm2 + comb
    k_mgemm<1><<<dim3(NT/128, 1), 256, MG_SMEM>>>(
        (const __nv_bfloat16*)p_hiddens, (const __nv_bfloat16*)p_Wm2s, bm2, (const float*)p_comb, (float*)p_out2, 768, 128);

    k_stats<<<NT/256, 256>>>((const float*)p_out2, 2);
    k_finalize<<<1, 128>>>(2, gn3, bn3);
    k_final<<<NT*CC/4/256, 256>>>((float*)d_out);
}